// round 4
// baseline (speedup 1.0000x reference)
#include <cuda_runtime.h>
#include <cuda_bf16.h>
#include <math.h>

// ---------------- problem constants ----------------
#define B_     16
#define J_     64
#define HM_    256            // heatmap H=W
#define NROWS  (B_ * J_)      // 1024
#define KIN    992            // 96 + 384 + 512
#define N1     1024
#define N2     512
#define N3     256
#define N4     224
#define CPOS   32

// ---------------- device scratch (no allocation allowed) ----------------
__device__ int   g_peak[NROWS];
__device__ float g_ms [NROWS * KIN];
__device__ float g_h1 [NROWS * N1];
__device__ float g_h2 [NROWS * N2];
__device__ float g_h3 [NROWS * N3];

// ---------------- kernel 1: per-(b,j) argmax over 256x256 ----------------
__global__ void argmax_kernel(const float* __restrict__ hm)
{
    __shared__ float sv[256];
    __shared__ int   si[256];

    const int bj = blockIdx.x;
    const float4* p = reinterpret_cast<const float4*>(hm + (size_t)bj * (HM_ * HM_));

    float best = __int_as_float(0xff800000);  // -inf
    int   bidx = 0;

    // 65536 floats = 16384 float4, 256 threads -> 64 each (ascending index
    // within a thread, so '>' keeps the first occurrence per-thread).
    for (int i = threadIdx.x; i < (HM_ * HM_ / 4); i += 256) {
        float4 v = p[i];
        int base = i * 4;
        if (v.x > best) { best = v.x; bidx = base;     }
        if (v.y > best) { best = v.y; bidx = base + 1; }
        if (v.z > best) { best = v.z; bidx = base + 2; }
        if (v.w > best) { best = v.w; bidx = base + 3; }
    }
    sv[threadIdx.x] = best;
    si[threadIdx.x] = bidx;
    __syncthreads();

    // tree reduce with first-occurrence (lowest index) tie-break
    for (int s = 128; s > 0; s >>= 1) {
        if (threadIdx.x < s) {
            float ov = sv[threadIdx.x + s];
            int   oi = si[threadIdx.x + s];
            float mv = sv[threadIdx.x];
            if (ov > mv || (ov == mv && oi < si[threadIdx.x])) {
                sv[threadIdx.x] = ov;
                si[threadIdx.x] = oi;
            }
        }
        __syncthreads();
    }
    if (threadIdx.x == 0) g_peak[bj] = si[0];
}

// ---------------- kernel 2: gathers (nearest pos_embed -> out tail, bilinear feats -> g_ms) ----------------
__device__ __forceinline__ void bilinear_feat(const float* __restrict__ f,
                                              int b, int bj, int C, int S,
                                              int coff, float gx, float gy)
{
    // mirror reference arithmetic: x = ((g + 1.0) * 0.5) * (S - 1)
    float xf = ((gx + 1.0f) * 0.5f) * (float)(S - 1);
    float yf = ((gy + 1.0f) * 0.5f) * (float)(S - 1);
    float x0f = floorf(xf), y0f = floorf(yf);
    float wx = xf - x0f,    wy = yf - y0f;
    int x0 = min(max((int)x0f, 0), S - 1);
    int x1 = min(max((int)x0f + 1, 0), S - 1);
    int y0 = min(max((int)y0f, 0), S - 1);
    int y1 = min(max((int)y0f + 1, 0), S - 1);

    float w00 = (1.0f - wx) * (1.0f - wy);
    float w01 = wx * (1.0f - wy);
    float w10 = (1.0f - wx) * wy;
    float w11 = wx * wy;

    for (int c = threadIdx.x; c < C; c += blockDim.x) {
        const float* chan = f + ((size_t)(b * C + c)) * S * S;
        float v00 = chan[y0 * S + x0];
        float v01 = chan[y0 * S + x1];
        float v10 = chan[y1 * S + x0];
        float v11 = chan[y1 * S + x1];
        g_ms[(size_t)bj * KIN + coff + c] = v00 * w00 + v01 * w01 + v10 * w10 + v11 * w11;
    }
}

__global__ void gather_kernel(const float* __restrict__ pos_embed,
                              const float* __restrict__ f1,
                              const float* __restrict__ f2,
                              const float* __restrict__ f3,
                              float* __restrict__ out)
{
    const int bj = blockIdx.x;
    const int b  = bj >> 6;
    const int j  = bj & 63;

    int idx = g_peak[bj];
    int px = idx & (HM_ - 1);
    int py = idx >> 8;

    float gx = ((float)px - 127.5f) / 127.5f;
    float gy = ((float)py - 127.5f) / 127.5f;

    // nearest sample of pos_embed -> out channels [224, 256)
    {
        float xr = ((gx + 1.0f) * 0.5f) * 255.0f;
        float yr = ((gy + 1.0f) * 0.5f) * 255.0f;
        int ix = min(max((int)rintf(xr), 0), HM_ - 1);  // rintf = half-even, matches jnp.round
        int iy = min(max((int)rintf(yr), 0), HM_ - 1);
        for (int c = threadIdx.x; c < CPOS; c += blockDim.x) {
            float v = pos_embed[((size_t)(b * CPOS + c)) * (HM_ * HM_) + iy * HM_ + ix];
            out[((size_t)(b * 256) + 224 + c) * J_ + j] = v;
        }
    }

    bilinear_feat(f1, b, bj,  96, 128,   0, gx, gy);
    bilinear_feat(f2, b, bj, 384,  64,  96, gx, gy);
    bilinear_feat(f3, b, bj, 512,  32, 480, gx, gy);
}

// ---------------- kernel 3: tiled SGEMM + bias + ReLU ----------------
// C[M,N] = relu(A[M,K] @ W[K,N] + bias). 64x64 tile, BK=16, 256 threads, 4x4 microtile.
// FINAL=true writes transposed into out: out[b, n, j] with m = b*64 + j.
template<bool FINAL>
__global__ __launch_bounds__(256) void gemm_relu_kernel(const float* __restrict__ A,
                                                        const float* __restrict__ W,
                                                        const float* __restrict__ bias,
                                                        float* __restrict__ C,
                                                        int M, int N, int K)
{
    const int BM = 64, BN = 64, BK = 16;
    __shared__ float As[BK][BM + 4];   // stride 68: conflict-spread, float4-aligned
    __shared__ float Bs[BK][BN + 4];

    const int tid = threadIdx.x;
    const int bm  = blockIdx.y * BM;
    const int bn  = blockIdx.x * BN;
    const int tx  = tid & 15;          // -> n micro
    const int ty  = tid >> 4;          // -> m micro

    // A load map: 64 rows x 16 k, one float4 per thread
    const int arow = tid >> 2;
    const int akv  = (tid & 3) * 4;
    // B load map: 16 k-rows x 64 n, one float4 per thread
    const int bkr  = tid >> 4;
    const int bnv  = (tid & 15) * 4;

    float acc[4][4] = {};

    for (int k0 = 0; k0 < K; k0 += BK) {
        // stage A (transposed into As[k][m])
        float4 av = *reinterpret_cast<const float4*>(A + (size_t)(bm + arow) * K + k0 + akv);
        As[akv + 0][arow] = av.x;
        As[akv + 1][arow] = av.y;
        As[akv + 2][arow] = av.z;
        As[akv + 3][arow] = av.w;

        // stage B (guard only the N edge; K,M always tile-aligned here)
        if (bn + bnv + 3 < N) {
            float4 wv = *reinterpret_cast<const float4*>(W + (size_t)(k0 + bkr) * N + bn + bnv);
            *reinterpret_cast<float4*>(&Bs[bkr][bnv]) = wv;
        } else {
            #pragma unroll
            for (int i = 0; i < 4; i++) {
                int n = bn + bnv + i;
                Bs[bkr][bnv + i] = (n < N) ? W[(size_t)(k0 + bkr) * N + n] : 0.0f;
            }
        }
        __syncthreads();

        #pragma unroll
        for (int k = 0; k < BK; k++) {
            float4 af = *reinterpret_cast<const float4*>(&As[k][ty * 4]);
            float4 bf = *reinterpret_cast<const float4*>(&Bs[k][tx * 4]);
            float a[4] = {af.x, af.y, af.z, af.w};
            float bb[4] = {bf.x, bf.y, bf.z, bf.w};
            #pragma unroll
            for (int i = 0; i < 4; i++)
                #pragma unroll
                for (int jj = 0; jj < 4; jj++)
                    acc[i][jj] += a[i] * bb[jj];
        }
        __syncthreads();
    }

    #pragma unroll
    for (int i = 0; i < 4; i++) {
        int m = bm + ty * 4 + i;
        #pragma unroll
        for (int jj = 0; jj < 4; jj++) {
            int n = bn + tx * 4 + jj;
            if (n < N) {
                float v = fmaxf(acc[i][jj] + bias[n], 0.0f);
                if (FINAL) {
                    int b = m >> 6, j = m & 63;
                    C[((size_t)(b * 256) + n) * J_ + j] = v;
                } else {
                    C[(size_t)m * N + n] = v;
                }
            }
        }
    }
}

// ---------------- launch ----------------
extern "C" void kernel_launch(void* const* d_in, const int* in_sizes, int n_in,
                              void* d_out, int out_size)
{
    const float* heatmap   = (const float*)d_in[0];
    const float* pos_embed = (const float*)d_in[1];
    const float* f1        = (const float*)d_in[2];
    const float* f2        = (const float*)d_in[3];
    const float* f3        = (const float*)d_in[4];
    const float* W1        = (const float*)d_in[5];
    const float* b1        = (const float*)d_in[6];
    const float* W2        = (const float*)d_in[7];
    const float* b2        = (const float*)d_in[8];
    const float* W3        = (const float*)d_in[9];
    const float* b3        = (const float*)d_in[10];
    const float* W4        = (const float*)d_in[11];
    const float* b4        = (const float*)d_in[12];
    float* out = (float*)d_out;

    float *ms, *h1, *h2, *h3;
    cudaGetSymbolAddress((void**)&ms, g_ms);
    cudaGetSymbolAddress((void**)&h1, g_h1);
    cudaGetSymbolAddress((void**)&h2, g_h2);
    cudaGetSymbolAddress((void**)&h3, g_h3);

    argmax_kernel<<<NROWS, 256>>>(heatmap);
    gather_kernel<<<NROWS, 256>>>(pos_embed, f1, f2, f3, out);

    gemm_relu_kernel<false><<<dim3(N1 / 64, NROWS / 64), 256>>>(ms, W1, b1, h1, NROWS, N1, KIN);
    gemm_relu_kernel<false><<<dim3(N2 / 64, NROWS / 64), 256>>>(h1, W2, b2, h2, NROWS, N2, N1);
    gemm_relu_kernel<false><<<dim3(N3 / 64, NROWS / 64), 256>>>(h2, W3, b3, h3, NROWS, N3, N2);
    gemm_relu_kernel<true ><<<dim3((N4 + 63) / 64, NROWS / 64), 256>>>(h3, W4, b4, out, NROWS, N4, N3);
}

// round 5
// speedup vs baseline: 1.1556x; 1.1556x over previous
#include <cuda_runtime.h>
#include <cuda_bf16.h>
#include <math.h>

// ---------------- problem constants ----------------
#define B_     16
#define J_     64
#define HM_    256            // heatmap H=W
#define NROWS  (B_ * J_)      // 1024
#define KIN    992            // 96 + 384 + 512
#define N1     1024
#define N2     512
#define N3     256
#define N4     224
#define CPOS   32

typedef unsigned long long ull_t;

// ---------------- device scratch (no allocation allowed) ----------------
__device__ float g_ms [NROWS * KIN];
__device__ float g_h1 [NROWS * N1];
__device__ float g_h2 [NROWS * N2];
__device__ float g_h3 [NROWS * N3];

// ---------------- f32x2 helpers (FFMA2 is PTX-only; ptxas won't auto-fuse) ----
__device__ __forceinline__ void fma2(ull_t& acc, ull_t a, ull_t b) {
    asm volatile("fma.rn.f32x2 %0, %1, %2, %0;" : "+l"(acc) : "l"(a), "l"(b));
}
__device__ __forceinline__ ull_t pack2(float v) {
    ull_t r; unsigned u = __float_as_uint(v);
    asm("mov.b64 %0, {%1, %1};" : "=l"(r) : "r"(u));
    return r;
}

// ---------------- kernel 1: fused per-(b,j) argmax + gathers ----------------
__device__ __forceinline__ void bilinear_feat(const float* __restrict__ f,
                                              int b, int bj, int C, int S,
                                              int coff, float gx, float gy)
{
    float xf = ((gx + 1.0f) * 0.5f) * (float)(S - 1);
    float yf = ((gy + 1.0f) * 0.5f) * (float)(S - 1);
    float x0f = floorf(xf), y0f = floorf(yf);
    float wx = xf - x0f,    wy = yf - y0f;
    int x0 = min(max((int)x0f, 0), S - 1);
    int x1 = min(max((int)x0f + 1, 0), S - 1);
    int y0 = min(max((int)y0f, 0), S - 1);
    int y1 = min(max((int)y0f + 1, 0), S - 1);

    float w00 = (1.0f - wx) * (1.0f - wy);
    float w01 = wx * (1.0f - wy);
    float w10 = (1.0f - wx) * wy;
    float w11 = wx * wy;

    for (int c = threadIdx.x; c < C; c += blockDim.x) {
        const float* chan = f + ((size_t)(b * C + c)) * S * S;
        float v00 = chan[y0 * S + x0];
        float v01 = chan[y0 * S + x1];
        float v10 = chan[y1 * S + x0];
        float v11 = chan[y1 * S + x1];
        g_ms[(size_t)bj * KIN + coff + c] = v00 * w00 + v01 * w01 + v10 * w10 + v11 * w11;
    }
}

__global__ void argmax_gather_kernel(const float* __restrict__ hm,
                                     const float* __restrict__ pos_embed,
                                     const float* __restrict__ f1,
                                     const float* __restrict__ f2,
                                     const float* __restrict__ f3,
                                     float* __restrict__ out)
{
    __shared__ float sv[256];
    __shared__ int   si[256];

    const int bj = blockIdx.x;
    const int b  = bj >> 6;
    const int j  = bj & 63;
    const float4* p = reinterpret_cast<const float4*>(hm + (size_t)bj * (HM_ * HM_));

    float best = __int_as_float(0xff800000);  // -inf
    int   bidx = 0;

    for (int i = threadIdx.x; i < (HM_ * HM_ / 4); i += 256) {
        float4 v = p[i];
        int base = i * 4;
        if (v.x > best) { best = v.x; bidx = base;     }
        if (v.y > best) { best = v.y; bidx = base + 1; }
        if (v.z > best) { best = v.z; bidx = base + 2; }
        if (v.w > best) { best = v.w; bidx = base + 3; }
    }
    sv[threadIdx.x] = best;
    si[threadIdx.x] = bidx;
    __syncthreads();

    for (int s = 128; s > 0; s >>= 1) {
        if (threadIdx.x < s) {
            float ov = sv[threadIdx.x + s];
            int   oi = si[threadIdx.x + s];
            float mv = sv[threadIdx.x];
            if (ov > mv || (ov == mv && oi < si[threadIdx.x])) {
                sv[threadIdx.x] = ov;
                si[threadIdx.x] = oi;
            }
        }
        __syncthreads();
    }

    const int idx = si[0];
    const int px = idx & (HM_ - 1);
    const int py = idx >> 8;
    const float gx = ((float)px - 127.5f) / 127.5f;
    const float gy = ((float)py - 127.5f) / 127.5f;

    // nearest sample of pos_embed -> out channels [224, 256)
    {
        float xr = ((gx + 1.0f) * 0.5f) * 255.0f;
        float yr = ((gy + 1.0f) * 0.5f) * 255.0f;
        int ix = min(max((int)rintf(xr), 0), HM_ - 1);
        int iy = min(max((int)rintf(yr), 0), HM_ - 1);
        for (int c = threadIdx.x; c < CPOS; c += blockDim.x) {
            float v = pos_embed[((size_t)(b * CPOS + c)) * (HM_ * HM_) + iy * HM_ + ix];
            out[((size_t)(b * 256) + 224 + c) * J_ + j] = v;
        }
    }

    bilinear_feat(f1, b, bj,  96, 128,   0, gx, gy);
    bilinear_feat(f2, b, bj, 384,  64,  96, gx, gy);
    bilinear_feat(f3, b, bj, 512,  32, 480, gx, gy);
}

// ---------------- kernel 2: f32x2 SGEMM + bias + ReLU, double-buffered ----------------
// C[M,N] = relu(A[M,K] @ W[K,N] + bias). BM=64, BK=32, 256 threads.
// BN/TN chosen per layer so grids fill the chip and all dims divide exactly.
// FINAL=true scatters transposed into out: out[b, n, j] with m = b*64 + j.
template<int BN, int TN, bool FINAL>
__global__ __launch_bounds__(256, 2) void gemm_f32x2(const float* __restrict__ A,
                                                     const float* __restrict__ W,
                                                     const float* __restrict__ bias,
                                                     float* __restrict__ C,
                                                     int N, int K)
{
    const int BM = 64, BK = 32, TM = 4;
    const int THN  = BN / TN;                 // 16 for both (64,4) and (32,2)
    const int NQB  = BN / 4;                  // float4 slots per B row
    const int NBF4 = (BK * BN / 4) / 256;     // B float4 loads per thread (2 or 1)
    const int NP   = TN / 2;                  // f32x2 pairs per m-row

    __shared__ float As[2][BK][BM + 4];       // As[k][m], +4: conflict spread, rows 16B-aligned
    __shared__ float Bs[2][BK][BN + 4];       // row stride (BN+4)*4 bytes: 272 or 144, both %16==0

    const int tid = threadIdx.x;
    const int bm  = blockIdx.y * BM;
    const int bn  = blockIdx.x * BN;
    const int tx  = tid % THN;
    const int ty  = tid / THN;
    const int m0  = ty * TM;
    const int n0  = tx * TN;

    float4 aReg[2], bReg[2];

    ull_t acc[TM][NP] = {};                   // packed (n, n+1) fp32 pairs

    // ---- staging helpers ----
    const int arow = tid >> 3;                // 0..31 then +32 for p=1? no: idx-based below
    (void)arow;

    // prologue: load + store chunk 0
    {
        #pragma unroll
        for (int p = 0; p < 2; p++) {
            int idx = tid + p * 256;          // 512 float4 slots for A
            int row = idx >> 3, kc = idx & 7;
            aReg[p] = *reinterpret_cast<const float4*>(A + (size_t)(bm + row) * K + kc * 4);
        }
        #pragma unroll
        for (int p = 0; p < NBF4; p++) {
            int idx = tid + p * 256;
            int kr = idx / NQB, nc = idx % NQB;
            bReg[p] = *reinterpret_cast<const float4*>(W + (size_t)kr * N + bn + nc * 4);
        }
        #pragma unroll
        for (int p = 0; p < 2; p++) {
            int idx = tid + p * 256;
            int row = idx >> 3, kc = idx & 7;
            As[0][kc * 4 + 0][row] = aReg[p].x;
            As[0][kc * 4 + 1][row] = aReg[p].y;
            As[0][kc * 4 + 2][row] = aReg[p].z;
            As[0][kc * 4 + 3][row] = aReg[p].w;
        }
        #pragma unroll
        for (int p = 0; p < NBF4; p++) {
            int idx = tid + p * 256;
            int kr = idx / NQB, nc = idx % NQB;
            *reinterpret_cast<float4*>(&Bs[0][kr][nc * 4]) = bReg[p];
        }
    }
    __syncthreads();

    const int nch = K / BK;
    for (int c = 0; c < nch; c++) {
        const int s = c & 1;
        if (c + 1 < nch) {
            const int k0 = (c + 1) * BK;
            #pragma unroll
            for (int p = 0; p < 2; p++) {
                int idx = tid + p * 256;
                int row = idx >> 3, kc = idx & 7;
                aReg[p] = *reinterpret_cast<const float4*>(A + (size_t)(bm + row) * K + k0 + kc * 4);
            }
            #pragma unroll
            for (int p = 0; p < NBF4; p++) {
                int idx = tid + p * 256;
                int kr = idx / NQB, nc = idx % NQB;
                bReg[p] = *reinterpret_cast<const float4*>(W + (size_t)(k0 + kr) * N + bn + nc * 4);
            }
        }

        #pragma unroll
        for (int k = 0; k < BK; k++) {
            float4 af = *reinterpret_cast<const float4*>(&As[s][k][m0]);
            ull_t b2[NP];
            if (TN == 4) {
                ulonglong2 bv = *reinterpret_cast<const ulonglong2*>(&Bs[s][k][n0]);
                b2[0] = bv.x; b2[NP - 1] = bv.y;
            } else {
                b2[0] = *reinterpret_cast<const ull_t*>(&Bs[s][k][n0]);
            }
            float am[4] = {af.x, af.y, af.z, af.w};
            #pragma unroll
            for (int i = 0; i < TM; i++) {
                ull_t a2 = pack2(am[i]);
                #pragma unroll
                for (int jp = 0; jp < NP; jp++) fma2(acc[i][jp], a2, b2[jp]);
            }
        }

        if (c + 1 < nch) {
            const int so = s ^ 1;
            #pragma unroll
            for (int p = 0; p < 2; p++) {
                int idx = tid + p * 256;
                int row = idx >> 3, kc = idx & 7;
                As[so][kc * 4 + 0][row] = aReg[p].x;
                As[so][kc * 4 + 1][row] = aReg[p].y;
                As[so][kc * 4 + 2][row] = aReg[p].z;
                As[so][kc * 4 + 3][row] = aReg[p].w;
            }
            #pragma unroll
            for (int p = 0; p < NBF4; p++) {
                int idx = tid + p * 256;
                int kr = idx / NQB, nc = idx % NQB;
                *reinterpret_cast<float4*>(&Bs[so][kr][nc * 4]) = bReg[p];
            }
        }
        __syncthreads();
    }

    // ---- epilogue: bias + ReLU (+ optional transpose scatter) ----
    #pragma unroll
    for (int i = 0; i < TM; i++) {
        const int m = bm + m0 + i;
        #pragma unroll
        for (int jp = 0; jp < NP; jp++) {
            const int n = bn + n0 + 2 * jp;
            float v0 = __uint_as_float((unsigned)(acc[i][jp]));
            float v1 = __uint_as_float((unsigned)(acc[i][jp] >> 32));
            v0 = fmaxf(v0 + bias[n],     0.0f);
            v1 = fmaxf(v1 + bias[n + 1], 0.0f);
            if (FINAL) {
                const int bb = m >> 6, jj = m & 63;
                C[((size_t)(bb * 256) + n    ) * J_ + jj] = v0;
                C[((size_t)(bb * 256) + n + 1) * J_ + jj] = v1;
            } else {
                *reinterpret_cast<float2*>(&C[(size_t)m * N + n]) = make_float2(v0, v1);
            }
        }
    }
}

// ---------------- launch ----------------
extern "C" void kernel_launch(void* const* d_in, const int* in_sizes, int n_in,
                              void* d_out, int out_size)
{
    const float* heatmap   = (const float*)d_in[0];
    const float* pos_embed = (const float*)d_in[1];
    const float* f1        = (const float*)d_in[2];
    const float* f2        = (const float*)d_in[3];
    const float* f3        = (const float*)d_in[4];
    const float* W1        = (const float*)d_in[5];
    const float* b1        = (const float*)d_in[6];
    const float* W2        = (const float*)d_in[7];
    const float* b2        = (const float*)d_in[8];
    const float* W3        = (const float*)d_in[9];
    const float* b3        = (const float*)d_in[10];
    const float* W4        = (const float*)d_in[11];
    const float* b4        = (const float*)d_in[12];
    float* out = (float*)d_out;

    float *ms, *h1, *h2, *h3;
    cudaGetSymbolAddress((void**)&ms, g_ms);
    cudaGetSymbolAddress((void**)&h1, g_h1);
    cudaGetSymbolAddress((void**)&h2, g_h2);
    cudaGetSymbolAddress((void**)&h3, g_h3);

    argmax_gather_kernel<<<NROWS, 256>>>(heatmap, pos_embed, f1, f2, f3, out);

    // L1: 1024x1024x992, BN=64 -> grid 16x16 = 256 blocks (2 CTA/SM)
    gemm_f32x2<64, 4, false><<<dim3(N1 / 64, NROWS / 64), 256>>>(ms, W1, b1, h1, N1, KIN);
    // L2: 1024x512x1024, BN=32 -> grid 16x16 = 256 blocks
    gemm_f32x2<32, 2, false><<<dim3(N2 / 32, NROWS / 64), 256>>>(h1, W2, b2, h2, N2, N1);
    // L3: 1024x256x512, BN=32 -> grid 8x16 = 128 blocks
    gemm_f32x2<32, 2, false><<<dim3(N3 / 32, NROWS / 64), 256>>>(h2, W3, b3, h3, N3, N2);
    // L4: 1024x224x256, BN=32 -> grid 7x16 = 112 blocks (224 % 32 == 0, no guards)
    gemm_f32x2<32, 2, true ><<<dim3(N4 / 32, NROWS / 64), 256>>>(h3, W4, b4, out, N4, N3);
}

// round 10
// speedup vs baseline: 1.5332x; 1.3267x over previous
#include <cuda_runtime.h>
#include <cuda_bf16.h>
#include <math.h>

// ---------------- problem constants ----------------
#define B_     16
#define J_     64
#define HM_    256
#define NROWS  (B_ * J_)      // 1024
#define KIN    992
#define N1     1024
#define N2     512
#define N3     256
#define N4     224
#define CPOS   32

// ---------------- device scratch ----------------
__device__ float g_ms [NROWS * KIN];
__device__ float g_h1 [NROWS * N1];
__device__ float g_h2 [NROWS * N2];
__device__ float g_h3 [NROWS * N3];

// ---------------- kernel 1: fused per-(b,j) argmax + gathers ----------------
__device__ __forceinline__ void bilinear_feat(const float* __restrict__ f,
                                              int b, int bj, int C, int S,
                                              int coff, float gx, float gy)
{
    float xf = ((gx + 1.0f) * 0.5f) * (float)(S - 1);
    float yf = ((gy + 1.0f) * 0.5f) * (float)(S - 1);
    float x0f = floorf(xf), y0f = floorf(yf);
    float wx = xf - x0f,    wy = yf - y0f;
    int x0 = min(max((int)x0f, 0), S - 1);
    int x1 = min(max((int)x0f + 1, 0), S - 1);
    int y0 = min(max((int)y0f, 0), S - 1);
    int y1 = min(max((int)y0f + 1, 0), S - 1);

    float w00 = (1.0f - wx) * (1.0f - wy);
    float w01 = wx * (1.0f - wy);
    float w10 = (1.0f - wx) * wy;
    float w11 = wx * wy;

    for (int c = threadIdx.x; c < C; c += blockDim.x) {
        const float* chan = f + ((size_t)(b * C + c)) * S * S;
        float v00 = chan[y0 * S + x0];
        float v01 = chan[y0 * S + x1];
        float v10 = chan[y1 * S + x0];
        float v11 = chan[y1 * S + x1];
        g_ms[(size_t)bj * KIN + coff + c] = v00 * w00 + v01 * w01 + v10 * w10 + v11 * w11;
    }
}

__global__ void argmax_gather_kernel(const float* __restrict__ hm,
                                     const float* __restrict__ pos_embed,
                                     const float* __restrict__ f1,
                                     const float* __restrict__ f2,
                                     const float* __restrict__ f3,
                                     float* __restrict__ out)
{
    __shared__ float sv[256];
    __shared__ int   si[256];

    const int bj = blockIdx.x;
    const int b  = bj >> 6;
    const int j  = bj & 63;
    const float4* p = reinterpret_cast<const float4*>(hm + (size_t)bj * (HM_ * HM_));

    float best = __int_as_float(0xff800000);
    int   bidx = 0;

    for (int i = threadIdx.x; i < (HM_ * HM_ / 4); i += 256) {
        float4 v = p[i];
        int base = i * 4;
        if (v.x > best) { best = v.x; bidx = base;     }
        if (v.y > best) { best = v.y; bidx = base + 1; }
        if (v.z > best) { best = v.z; bidx = base + 2; }
        if (v.w > best) { best = v.w; bidx = base + 3; }
    }
    sv[threadIdx.x] = best;
    si[threadIdx.x] = bidx;
    __syncthreads();

    for (int s = 128; s > 0; s >>= 1) {
        if (threadIdx.x < s) {
            float ov = sv[threadIdx.x + s];
            int   oi = si[threadIdx.x + s];
            float mv = sv[threadIdx.x];
            if (ov > mv || (ov == mv && oi < si[threadIdx.x])) {
                sv[threadIdx.x] = ov;
                si[threadIdx.x] = oi;
            }
        }
        __syncthreads();
    }

    const int idx = si[0];
    const int px = idx & (HM_ - 1);
    const int py = idx >> 8;
    const float gx = ((float)px - 127.5f) / 127.5f;
    const float gy = ((float)py - 127.5f) / 127.5f;

    {
        float xr = ((gx + 1.0f) * 0.5f) * 255.0f;
        float yr = ((gy + 1.0f) * 0.5f) * 255.0f;
        int ix = min(max((int)rintf(xr), 0), HM_ - 1);
        int iy = min(max((int)rintf(yr), 0), HM_ - 1);
        for (int c = threadIdx.x; c < CPOS; c += blockDim.x) {
            float v = pos_embed[((size_t)(b * CPOS + c)) * (HM_ * HM_) + iy * HM_ + ix];
            out[((size_t)(b * 256) + 224 + c) * J_ + j] = v;
        }
    }

    bilinear_feat(f1, b, bj,  96, 128,   0, gx, gy);
    bilinear_feat(f2, b, bj, 384,  64,  96, gx, gy);
    bilinear_feat(f3, b, bj, 512,  32, 480, gx, gy);
}

// ---------------- kernel 2: bf16x3 tensor-core GEMM + bias + ReLU ----------------
// C[M,N] = relu(A @ W + b) with fp32-equivalent precision via bf16 hi/lo split:
//   C ~= Ah*Wh + Ah*Wl + Al*Wh   (fp32 accumulate; dropped terms ~2^-18 rel)
// BM=64, BN=32, BK=32, 128 threads (4 warps, 2x2), warp tile 32x16 (2x2 m16n8k16).
#define BM   64
#define BN   32
#define BK   32
#define AROW 40   // padded bf16 elems per smem row (80B stride -> conflict-spread ldmatrix)

__device__ __forceinline__ void split_bf(float v, unsigned short& h, unsigned short& l)
{
    __nv_bfloat16 hb = __float2bfloat16(v);           // rn
    h = __bfloat16_as_ushort(hb);
    float r = v - __bfloat162float(hb);
    l = __bfloat16_as_ushort(__float2bfloat16(r));
}

#define LDSM4(R, ADDR) \
    asm volatile("ldmatrix.sync.aligned.m8n8.x4.shared.b16 {%0,%1,%2,%3}, [%4];" \
                 : "=r"((R)[0]), "=r"((R)[1]), "=r"((R)[2]), "=r"((R)[3]) : "r"(ADDR))

#define MMA16816(D, A, B0, B1) \
    asm volatile("mma.sync.aligned.m16n8k16.row.col.f32.bf16.bf16.f32 " \
                 "{%0,%1,%2,%3}, {%4,%5,%6,%7}, {%8,%9}, {%0,%1,%2,%3};" \
                 : "+f"((D)[0]), "+f"((D)[1]), "+f"((D)[2]), "+f"((D)[3]) \
                 : "r"((A)[0]), "r"((A)[1]), "r"((A)[2]), "r"((A)[3]), "r"(B0), "r"(B1))

template<bool FINAL>
__global__ __launch_bounds__(128) void gemm_bf16x3(const float* __restrict__ A,
                                                   const float* __restrict__ W,
                                                   const float* __restrict__ bias,
                                                   float* __restrict__ C,
                                                   int N, int K)
{
    // smem: [buf][hi/lo] planes
    __shared__ __align__(16) unsigned short sA[2][2][BM * AROW];
    __shared__ __align__(16) unsigned short sB[2][2][BN * AROW];

    const int tid  = threadIdx.x;
    const int wid  = tid >> 5;
    const int lane = tid & 31;
    const int wm   = wid >> 1;          // 0..1
    const int wn   = wid & 1;           // 0..1
    const int bm   = blockIdx.y * BM;
    const int bn   = blockIdx.x * BN;
    const int M0   = wm * 32;
    const int N0   = wn * 16;
    const int gid  = lane >> 2;
    const int tig  = lane & 3;

    // ldmatrix lane byte offsets within a plane (x4 tiles: [m0-7,k0-7],[m8-15,k0-7],[m0-7,k8-15],[m8-15,k8-15])
    const int ltile = lane >> 3, rin = lane & 7;
    const int rsel  = (ltile & 1) ? 8 : 0;
    const int ksel  = (ltile >= 2) ? 8 : 0;
    int aoff[2];
    aoff[0] = ((M0 +      rsel + rin) * AROW + ksel) * 2;
    aoff[1] = ((M0 + 16 + rsel + rin) * AROW + ksel) * 2;
    const int boff = ((N0 + rsel + rin) * AROW + ksel) * 2;

    const unsigned aBase = (unsigned)__cvta_generic_to_shared(&sA[0][0][0]);
    const unsigned bBase = (unsigned)__cvta_generic_to_shared(&sB[0][0][0]);
    const unsigned A_BUF = 2u * BM * AROW * 2u;   // bytes per buf (both planes)
    const unsigned A_PL  = (unsigned)BM * AROW * 2u;
    const unsigned B_BUF = 2u * BN * AROW * 2u;
    const unsigned B_PL  = (unsigned)BN * AROW * 2u;

    float acc[2][2][4] = {};
    float4 aReg[4];
    float  wReg[8];

    // ---- global load (chunk k0) ----
    auto load_globals = [&](int k0) {
        #pragma unroll
        for (int i = 0; i < 4; i++) {
            int idx = tid + i * 128;
            int row = idx >> 3, kq = idx & 7;
            aReg[i] = *reinterpret_cast<const float4*>(A + (size_t)(bm + row) * K + k0 + kq * 4);
        }
        #pragma unroll
        for (int i = 0; i < 4; i++) {
            int k = k0 + 2 * (wid + i * 4);
            wReg[2 * i]     = W[(size_t)k * N + bn + lane];
            wReg[2 * i + 1] = W[(size_t)(k + 1) * N + bn + lane];
        }
    };

    // ---- stage regs -> smem buf ----
    auto stage = [&](int buf) {
        #pragma unroll
        for (int i = 0; i < 4; i++) {
            int idx = tid + i * 128;
            int row = idx >> 3, kq = idx & 7;
            unsigned short h0, l0, h1, l1, h2, l2, h3, l3;
            split_bf(aReg[i].x, h0, l0);
            split_bf(aReg[i].y, h1, l1);
            split_bf(aReg[i].z, h2, l2);
            split_bf(aReg[i].w, h3, l3);
            unsigned* ph = reinterpret_cast<unsigned*>(&sA[buf][0][row * AROW + kq * 4]);
            unsigned* pl = reinterpret_cast<unsigned*>(&sA[buf][1][row * AROW + kq * 4]);
            ph[0] = (unsigned)h0 | ((unsigned)h1 << 16);
            ph[1] = (unsigned)h2 | ((unsigned)h3 << 16);
            pl[0] = (unsigned)l0 | ((unsigned)l1 << 16);
            pl[1] = (unsigned)l2 | ((unsigned)l3 << 16);
        }
        #pragma unroll
        for (int i = 0; i < 4; i++) {
            int kp = wid + i * 4;      // k-pair index 0..15
            unsigned short h0, l0, h1, l1;
            split_bf(wReg[2 * i],     h0, l0);
            split_bf(wReg[2 * i + 1], h1, l1);
            // B stored [n][k] (k contiguous) so B frags come from plain ldmatrix
            unsigned* ph = reinterpret_cast<unsigned*>(&sB[buf][0][lane * AROW + kp * 2]);
            unsigned* pl = reinterpret_cast<unsigned*>(&sB[buf][1][lane * AROW + kp * 2]);
            ph[0] = (unsigned)h0 | ((unsigned)h1 << 16);
            pl[0] = (unsigned)l0 | ((unsigned)l1 << 16);
        }
    };

    load_globals(0);
    stage(0);
    __syncthreads();

    const int nch = K / BK;
    for (int c = 0; c < nch; c++) {
        const int buf = c & 1;
        if (c + 1 < nch) load_globals((c + 1) * BK);

        const unsigned aHi = aBase + buf * A_BUF;
        const unsigned aLo = aHi + A_PL;
        const unsigned bHi = bBase + buf * B_BUF;
        const unsigned bLo = bHi + B_PL;

        #pragma unroll
        for (int kk = 0; kk < BK; kk += 16) {
            unsigned a_hi[2][4], a_lo[2][4], b_hi[4], b_lo[4];
            #pragma unroll
            for (int mi = 0; mi < 2; mi++) {
                LDSM4(a_hi[mi], aHi + aoff[mi] + kk * 2);
                LDSM4(a_lo[mi], aLo + aoff[mi] + kk * 2);
            }
            LDSM4(b_hi, bHi + boff + kk * 2);
            LDSM4(b_lo, bLo + boff + kk * 2);

            #pragma unroll
            for (int mi = 0; mi < 2; mi++)
                #pragma unroll
                for (int ni = 0; ni < 2; ni++) {
                    MMA16816(acc[mi][ni], a_hi[mi], b_hi[ni], b_hi[ni + 2]);
                    MMA16816(acc[mi][ni], a_hi[mi], b_lo[ni], b_lo[ni + 2]);
                    MMA16816(acc[mi][ni], a_lo[mi], b_hi[ni], b_hi[ni + 2]);
                }
        }

        if (c + 1 < nch) stage(buf ^ 1);
        __syncthreads();
    }

    // ---- epilogue: bias + ReLU (+ transpose scatter for the final layer) ----
    #pragma unroll
    for (int mi = 0; mi < 2; mi++) {
        const int m0r = bm + M0 + mi * 16 + gid;
        #pragma unroll
        for (int ni = 0; ni < 2; ni++) {
            const int nb = bn + N0 + ni * 8 + 2 * tig;
            const float bv0 = bias[nb], bv1 = bias[nb + 1];
            float v00 = fmaxf(acc[mi][ni][0] + bv0, 0.0f);
            float v01 = fmaxf(acc[mi][ni][1] + bv1, 0.0f);
            float v10 = fmaxf(acc[mi][ni][2] + bv0, 0.0f);
            float v11 = fmaxf(acc[mi][ni][3] + bv1, 0.0f);
            if (FINAL) {
                int b0 = m0r >> 6, j0 = m0r & 63;
                int m1 = m0r + 8;
                int b1 = m1 >> 6, j1 = m1 & 63;
                C[((size_t)(b0 * 256) + nb    ) * J_ + j0] = v00;
                C[((size_t)(b0 * 256) + nb + 1) * J_ + j0] = v01;
                C[((size_t)(b1 * 256) + nb    ) * J_ + j1] = v10;
                C[((size_t)(b1 * 256) + nb + 1) * J_ + j1] = v11;
            } else {
                *reinterpret_cast<float2*>(&C[(size_t)m0r * N + nb])       = make_float2(v00, v01);
                *reinterpret_cast<float2*>(&C[(size_t)(m0r + 8) * N + nb]) = make_float2(v10, v11);
            }
        }
    }
}

// ---------------- launch ----------------
extern "C" void kernel_launch(void* const* d_in, const int* in_sizes, int n_in,
                              void* d_out, int out_size)
{
    const float* heatmap   = (const float*)d_in[0];
    const float* pos_embed = (const float*)d_in[1];
    const float* f1        = (const float*)d_in[2];
    const float* f2        = (const float*)d_in[3];
    const float* f3        = (const float*)d_in[4];
    const float* W1        = (const float*)d_in[5];
    const float* b1        = (const float*)d_in[6];
    const float* W2        = (const float*)d_in[7];
    const float* b2        = (const float*)d_in[8];
    const float* W3        = (const float*)d_in[9];
    const float* b3        = (const float*)d_in[10];
    const float* W4        = (const float*)d_in[11];
    const float* b4        = (const float*)d_in[12];
    float* out = (float*)d_out;

    float *ms, *h1, *h2, *h3;
    cudaGetSymbolAddress((void**)&ms, g_ms);
    cudaGetSymbolAddress((void**)&h1, g_h1);
    cudaGetSymbolAddress((void**)&h2, g_h2);
    cudaGetSymbolAddress((void**)&h3, g_h3);

    argmax_gather_kernel<<<NROWS, 256>>>(heatmap, pos_embed, f1, f2, f3, out);

    gemm_bf16x3<false><<<dim3(N1 / BN, NROWS / BM), 128>>>(ms, W1, b1, h1, N1, KIN);
    gemm_bf16x3<false><<<dim3(N2 / BN, NROWS / BM), 128>>>(h1, W2, b2, h2, N2, N1);
    gemm_bf16x3<false><<<dim3(N3 / BN, NROWS / BM), 128>>>(h2, W3, b3, h3, N3, N2);
    gemm_bf16x3<true ><<<dim3(N4 / BN, NROWS / BM), 128>>>(h3, W4, b4, out, N4, N3);
}

// round 15
// speedup vs baseline: 1.7757x; 1.1582x over previous
#include <cuda_runtime.h>
#include <cuda_bf16.h>
#include <math.h>

// ---------------- problem constants ----------------
#define B_     16
#define J_     64
#define HM_    256
#define NROWS  (B_ * J_)      // 1024
#define KIN    992
#define N1     1024
#define N2     512
#define N3     256
#define N4     224
#define CPOS   32

typedef unsigned short ush;

// ---------------- device scratch: bf16 hi/lo planes ----------------
__device__ ush g_ms_h[NROWS * KIN],  g_ms_l[NROWS * KIN];
__device__ ush g_h1_h[NROWS * N1],   g_h1_l[NROWS * N1];
__device__ ush g_h2_h[NROWS * N2],   g_h2_l[NROWS * N2];
__device__ ush g_h3_h[NROWS * N3],   g_h3_l[NROWS * N3];
__device__ ush g_w1_h[KIN * N1], g_w1_l[KIN * N1];
__device__ ush g_w2_h[N1 * N2],  g_w2_l[N1 * N2];
__device__ ush g_w3_h[N2 * N3],  g_w3_l[N2 * N3];
__device__ ush g_w4_h[N3 * N4],  g_w4_l[N3 * N4];

__device__ __forceinline__ void split_bf(float v, ush& h, ush& l)
{
    __nv_bfloat16 hb = __float2bfloat16(v);           // rn
    h = __bfloat16_as_ushort(hb);
    float r = v - __bfloat162float(hb);
    l = __bfloat16_as_ushort(__float2bfloat16(r));
}

// ---------------- weight transpose + hi/lo split:  W[k][n] -> wh/wl[n][k] ----------------
__global__ void wsplit_kernel(const float* __restrict__ W, ush* __restrict__ wh,
                              ush* __restrict__ wl, int K, int N)
{
    __shared__ float tile[32][33];
    const int kt = blockIdx.y * 32, nt = blockIdx.x * 32;
    const int tx = threadIdx.x, ty = threadIdx.y;     // 32 x 8
    #pragma unroll
    for (int i = 0; i < 4; i++)
        tile[ty + i * 8][tx] = W[(size_t)(kt + ty + i * 8) * N + nt + tx];
    __syncthreads();
    #pragma unroll
    for (int i = 0; i < 4; i++) {
        int n = nt + ty + i * 8, k = kt + tx;
        ush h, l; split_bf(tile[tx][ty + i * 8], h, l);
        wh[(size_t)n * K + k] = h;
        wl[(size_t)n * K + k] = l;
    }
}

// ---------------- kernel 1: fused per-(b,j) argmax + gathers (emit hi/lo) ----------------
__device__ __forceinline__ void bilinear_feat(const float* __restrict__ f,
                                              int b, int bj, int C, int S,
                                              int coff, float gx, float gy)
{
    float xf = ((gx + 1.0f) * 0.5f) * (float)(S - 1);
    float yf = ((gy + 1.0f) * 0.5f) * (float)(S - 1);
    float x0f = floorf(xf), y0f = floorf(yf);
    float wx = xf - x0f,    wy = yf - y0f;
    int x0 = min(max((int)x0f, 0), S - 1);
    int x1 = min(max((int)x0f + 1, 0), S - 1);
    int y0 = min(max((int)y0f, 0), S - 1);
    int y1 = min(max((int)y0f + 1, 0), S - 1);

    float w00 = (1.0f - wx) * (1.0f - wy);
    float w01 = wx * (1.0f - wy);
    float w10 = (1.0f - wx) * wy;
    float w11 = wx * wy;

    for (int c = threadIdx.x; c < C; c += blockDim.x) {
        const float* chan = f + ((size_t)(b * C + c)) * S * S;
        float v = chan[y0 * S + x0] * w00 + chan[y0 * S + x1] * w01
                + chan[y1 * S + x0] * w10 + chan[y1 * S + x1] * w11;
        ush h, l; split_bf(v, h, l);
        g_ms_h[(size_t)bj * KIN + coff + c] = h;
        g_ms_l[(size_t)bj * KIN + coff + c] = l;
    }
}

__global__ void argmax_gather_kernel(const float* __restrict__ hm,
                                     const float* __restrict__ pos_embed,
                                     const float* __restrict__ f1,
                                     const float* __restrict__ f2,
                                     const float* __restrict__ f3,
                                     float* __restrict__ out)
{
    __shared__ float sv[256];
    __shared__ int   si[256];

    const int bj = blockIdx.x;
    const int b  = bj >> 6;
    const int j  = bj & 63;
    const float4* p = reinterpret_cast<const float4*>(hm + (size_t)bj * (HM_ * HM_));

    float best = __int_as_float(0xff800000);
    int   bidx = 0;

    for (int i = threadIdx.x; i < (HM_ * HM_ / 4); i += 256) {
        float4 v = p[i];
        int base = i * 4;
        if (v.x > best) { best = v.x; bidx = base;     }
        if (v.y > best) { best = v.y; bidx = base + 1; }
        if (v.z > best) { best = v.z; bidx = base + 2; }
        if (v.w > best) { best = v.w; bidx = base + 3; }
    }
    sv[threadIdx.x] = best;
    si[threadIdx.x] = bidx;
    __syncthreads();

    for (int s = 128; s > 0; s >>= 1) {
        if (threadIdx.x < s) {
            float ov = sv[threadIdx.x + s];
            int   oi = si[threadIdx.x + s];
            float mv = sv[threadIdx.x];
            if (ov > mv || (ov == mv && oi < si[threadIdx.x])) {
                sv[threadIdx.x] = ov;
                si[threadIdx.x] = oi;
            }
        }
        __syncthreads();
    }

    const int idx = si[0];
    const int px = idx & (HM_ - 1);
    const int py = idx >> 8;
    const float gx = ((float)px - 127.5f) / 127.5f;
    const float gy = ((float)py - 127.5f) / 127.5f;

    {
        float xr = ((gx + 1.0f) * 0.5f) * 255.0f;
        float yr = ((gy + 1.0f) * 0.5f) * 255.0f;
        int ix = min(max((int)rintf(xr), 0), HM_ - 1);
        int iy = min(max((int)rintf(yr), 0), HM_ - 1);
        for (int c = threadIdx.x; c < CPOS; c += blockDim.x) {
            float v = pos_embed[((size_t)(b * CPOS + c)) * (HM_ * HM_) + iy * HM_ + ix];
            out[((size_t)(b * 256) + 224 + c) * J_ + j] = v;
        }
    }

    bilinear_feat(f1, b, bj,  96, 128,   0, gx, gy);
    bilinear_feat(f2, b, bj, 384,  64,  96, gx, gy);
    bilinear_feat(f3, b, bj, 512,  32, 480, gx, gy);
}

// ---------------- kernel 2: pre-split bf16x3 tensor-core GEMM ----------------
// C = relu(A @ W + b); A,W given as bf16 hi/lo planes, A[m][k], W[n][k].
// BM=BN=BK=32, 128 threads (4 warps 2x2, warp tile 16x16), 3-stage cp.async.
#define BM    32
#define BN    32
#define BK    32
#define AROW  40                 // padded elems/row: 80B stride (16B-aligned, conflict-spread)
#define PLB   (32 * AROW * 2)    // bytes per plane per stage (2560)

#define CP16(dst, src) asm volatile("cp.async.cg.shared.global [%0], [%1], 16;" :: "r"(dst), "l"(src))
#define CP_COMMIT()    asm volatile("cp.async.commit_group;")
#define CP_WAIT(n)     asm volatile("cp.async.wait_group %0;" :: "n"(n))

#define LDSM4(R, ADDR) \
    asm volatile("ldmatrix.sync.aligned.m8n8.x4.shared.b16 {%0,%1,%2,%3}, [%4];" \
                 : "=r"((R)[0]), "=r"((R)[1]), "=r"((R)[2]), "=r"((R)[3]) : "r"(ADDR))

#define MMA16816(D, A, B0, B1) \
    asm volatile("mma.sync.aligned.m16n8k16.row.col.f32.bf16.bf16.f32 " \
                 "{%0,%1,%2,%3}, {%4,%5,%6,%7}, {%8,%9}, {%0,%1,%2,%3};" \
                 : "+f"((D)[0]), "+f"((D)[1]), "+f"((D)[2]), "+f"((D)[3]) \
                 : "r"((A)[0]), "r"((A)[1]), "r"((A)[2]), "r"((A)[3]), "r"(B0), "r"(B1))

template<bool FINAL>
__global__ __launch_bounds__(128) void gemm_bf16x3(
    const ush* __restrict__ Ah, const ush* __restrict__ Al,
    const ush* __restrict__ Wh, const ush* __restrict__ Wl,
    const float* __restrict__ bias,
    ush* __restrict__ Ch, ush* __restrict__ Cl,
    float* __restrict__ Cf, int N, int K)
{
    __shared__ __align__(16) ush sA[3][2][32 * AROW];
    __shared__ __align__(16) ush sB[3][2][32 * AROW];

    const int tid  = threadIdx.x;
    const int wid  = tid >> 5;
    const int lane = tid & 31;
    const int bm   = blockIdx.y * BM;
    const int bn   = blockIdx.x * BN;
    const int M0   = (wid >> 1) * 16;
    const int N0   = (wid & 1) * 16;
    const int gid  = lane >> 2;
    const int tig  = lane & 3;

    // cp.async mapping: thread -> (row 0..31, 16B quad 0..3)
    const int row = tid >> 2, kq = tid & 3;
    const ush* aSrcH = Ah + (size_t)(bm + row) * K + kq * 8;
    const ush* aSrcL = Al + (size_t)(bm + row) * K + kq * 8;
    const ush* bSrcH = Wh + (size_t)(bn + row) * K + kq * 8;
    const ush* bSrcL = Wl + (size_t)(bn + row) * K + kq * 8;

    const unsigned aBase = (unsigned)__cvta_generic_to_shared(&sA[0][0][0]);
    const unsigned bBase = (unsigned)__cvta_generic_to_shared(&sB[0][0][0]);
    const unsigned dOff  = (unsigned)(row * AROW + kq * 8) * 2;

    // ldmatrix x4 lane offsets: tiles (r0-7,k0-7),(r8-15,k0-7),(r0-7,k8-15),(r8-15,k8-15)
    const int ltile = lane >> 3, rin = lane & 7;
    const int rsel  = (ltile & 1) ? 8 : 0;
    const int ksel  = (ltile >= 2) ? 8 : 0;
    const unsigned aoff = (unsigned)(((M0 + rsel + rin) * AROW + ksel) * 2);
    const unsigned boff = (unsigned)(((N0 + rsel + rin) * AROW + ksel) * 2);

    float acc[2][4] = {};

    const int nch = K / BK;
    auto issue = [&](int c) {
        const int st = c % 3;
        const int k0 = c * BK;
        CP16(aBase + (st * 2 + 0) * PLB + dOff, aSrcH + k0);
        CP16(aBase + (st * 2 + 1) * PLB + dOff, aSrcL + k0);
        CP16(bBase + (st * 2 + 0) * PLB + dOff, bSrcH + k0);
        CP16(bBase + (st * 2 + 1) * PLB + dOff, bSrcL + k0);
        CP_COMMIT();
    };

    issue(0);
    issue(1);

    for (int c = 0; c < nch; c++) {
        if (c < nch - 1) { CP_WAIT(1); } else { CP_WAIT(0); }
        __syncthreads();

        const int st = c % 3;
        const unsigned aH = aBase + (st * 2 + 0) * PLB;
        const unsigned aL = aH + PLB;
        const unsigned bH = bBase + (st * 2 + 0) * PLB;
        const unsigned bL = bH + PLB;

        #pragma unroll
        for (int kk = 0; kk < BK; kk += 16) {
            unsigned a_hi[4], a_lo[4], b_hi[4], b_lo[4];
            LDSM4(a_hi, aH + aoff + kk * 2);
            LDSM4(a_lo, aL + aoff + kk * 2);
            LDSM4(b_hi, bH + boff + kk * 2);
            LDSM4(b_lo, bL + boff + kk * 2);
            #pragma unroll
            for (int ni = 0; ni < 2; ni++) {
                MMA16816(acc[ni], a_hi, b_hi[ni], b_hi[ni + 2]);
                MMA16816(acc[ni], a_hi, b_lo[ni], b_lo[ni + 2]);
                MMA16816(acc[ni], a_lo, b_hi[ni], b_hi[ni + 2]);
            }
        }

        if (c + 2 < nch) issue(c + 2);
    }

    // ---- epilogue ----
    const int r0 = bm + M0 + gid;
    const int r1 = r0 + 8;
    #pragma unroll
    for (int ni = 0; ni < 2; ni++) {
        const int n = bn + N0 + ni * 8 + tig * 2;
        const float bv0 = bias[n], bv1 = bias[n + 1];
        float v00 = fmaxf(acc[ni][0] + bv0, 0.0f);
        float v01 = fmaxf(acc[ni][1] + bv1, 0.0f);
        float v10 = fmaxf(acc[ni][2] + bv0, 0.0f);
        float v11 = fmaxf(acc[ni][3] + bv1, 0.0f);
        if (FINAL) {
            const int b0 = r0 >> 6, j0 = r0 & 63;
            const int b1 = r1 >> 6, j1 = r1 & 63;
            Cf[((size_t)(b0 * 256) + n    ) * J_ + j0] = v00;
            Cf[((size_t)(b0 * 256) + n + 1) * J_ + j0] = v01;
            Cf[((size_t)(b1 * 256) + n    ) * J_ + j1] = v10;
            Cf[((size_t)(b1 * 256) + n + 1) * J_ + j1] = v11;
        } else {
            ush h0, l0, h1, l1;
            split_bf(v00, h0, l0); split_bf(v01, h1, l1);
            *reinterpret_cast<unsigned*>(&Ch[(size_t)r0 * N + n]) = (unsigned)h0 | ((unsigned)h1 << 16);
            *reinterpret_cast<unsigned*>(&Cl[(size_t)r0 * N + n]) = (unsigned)l0 | ((unsigned)l1 << 16);
            split_bf(v10, h0, l0); split_bf(v11, h1, l1);
            *reinterpret_cast<unsigned*>(&Ch[(size_t)r1 * N + n]) = (unsigned)h0 | ((unsigned)h1 << 16);
            *reinterpret_cast<unsigned*>(&Cl[(size_t)r1 * N + n]) = (unsigned)l0 | ((unsigned)l1 << 16);
        }
    }
}

// ---------------- launch ----------------
extern "C" void kernel_launch(void* const* d_in, const int* in_sizes, int n_in,
                              void* d_out, int out_size)
{
    const float* heatmap   = (const float*)d_in[0];
    const float* pos_embed = (const float*)d_in[1];
    const float* f1        = (const float*)d_in[2];
    const float* f2        = (const float*)d_in[3];
    const float* f3        = (const float*)d_in[4];
    const float* W1        = (const float*)d_in[5];
    const float* b1        = (const float*)d_in[6];
    const float* W2        = (const float*)d_in[7];
    const float* b2        = (const float*)d_in[8];
    const float* W3        = (const float*)d_in[9];
    const float* b3        = (const float*)d_in[10];
    const float* W4        = (const float*)d_in[11];
    const float* b4        = (const float*)d_in[12];
    float* out = (float*)d_out;

    ush *msh, *msl, *h1h, *h1l, *h2h, *h2l, *h3h, *h3l;
    ush *w1h, *w1l, *w2h, *w2l, *w3h, *w3l, *w4h, *w4l;
    cudaGetSymbolAddress((void**)&msh, g_ms_h); cudaGetSymbolAddress((void**)&msl, g_ms_l);
    cudaGetSymbolAddress((void**)&h1h, g_h1_h); cudaGetSymbolAddress((void**)&h1l, g_h1_l);
    cudaGetSymbolAddress((void**)&h2h, g_h2_h); cudaGetSymbolAddress((void**)&h2l, g_h2_l);
    cudaGetSymbolAddress((void**)&h3h, g_h3_h); cudaGetSymbolAddress((void**)&h3l, g_h3_l);
    cudaGetSymbolAddress((void**)&w1h, g_w1_h); cudaGetSymbolAddress((void**)&w1l, g_w1_l);
    cudaGetSymbolAddress((void**)&w2h, g_w2_h); cudaGetSymbolAddress((void**)&w2l, g_w2_l);
    cudaGetSymbolAddress((void**)&w3h, g_w3_h); cudaGetSymbolAddress((void**)&w3l, g_w3_l);
    cudaGetSymbolAddress((void**)&w4h, g_w4_h); cudaGetSymbolAddress((void**)&w4l, g_w4_l);

    const dim3 wsblk(32, 8);
    wsplit_kernel<<<dim3(N1 / 32, KIN / 32), wsblk>>>(W1, w1h, w1l, KIN, N1);
    wsplit_kernel<<<dim3(N2 / 32, N1 / 32),  wsblk>>>(W2, w2h, w2l, N1, N2);
    wsplit_kernel<<<dim3(N3 / 32, N2 / 32),  wsblk>>>(W3, w3h, w3l, N2, N3);
    wsplit_kernel<<<dim3(N4 / 32, N3 / 32),  wsblk>>>(W4, w4h, w4l, N3, N4);

    argmax_gather_kernel<<<NROWS, 256>>>(heatmap, pos_embed, f1, f2, f3, out);

    gemm_bf16x3<false><<<dim3(N1 / BN, NROWS / BM), 128>>>(msh, msl, w1h, w1l, b1, h1h, h1l, nullptr, N1, KIN);
    gemm_bf16x3<false><<<dim3(N2 / BN, NROWS / BM), 128>>>(h1h, h1l, w2h, w2l, b2, h2h, h2l, nullptr, N2, N1);
    gemm_bf16x3<false><<<dim3(N3 / BN, NROWS / BM), 128>>>(h2h, h2l, w3h, w3l, b3, h3h, h3l, nullptr, N3, N2);
    gemm_bf16x3<true ><<<dim3(N4 / BN, NROWS / BM), 128>>>(h3h, h3l, w4h, w4l, b4, nullptr, nullptr, out, N4, N3);
}

// round 17
// speedup vs baseline: 1.8473x; 1.0403x over previous
#include <cuda_runtime.h>
#include <cuda_bf16.h>
#include <math.h>

// ---------------- problem constants ----------------
#define B_     16
#define J_     64
#define HM_    256
#define NROWS  (B_ * J_)      // 1024
#define KIN    992
#define N1     1024
#define N2     512
#define N3     256
#define N4     224
#define CPOS   32

// weight-split tile counts (32x32 tiles): n-tiles x k-tiles
#define WT1    (32 * 31)      // 992
#define WT2    (16 * 32)      // 512
#define WT3    (8 * 16)       // 128
#define WT4    (7 * 8)        // 56
#define WT_ALL (WT1 + WT2 + WT3 + WT4)   // 1688

typedef unsigned short ush;

// ---------------- device scratch: bf16 hi/lo planes ----------------
__device__ ush g_ms_h[NROWS * KIN],  g_ms_l[NROWS * KIN];
__device__ ush g_h1_h[NROWS * N1],   g_h1_l[NROWS * N1];
__device__ ush g_h2_h[NROWS * N2],   g_h2_l[NROWS * N2];
__device__ ush g_h3_h[NROWS * N3],   g_h3_l[NROWS * N3];
__device__ ush g_w1_h[KIN * N1], g_w1_l[KIN * N1];
__device__ ush g_w2_h[N1 * N2],  g_w2_l[N1 * N2];
__device__ ush g_w3_h[N2 * N3],  g_w3_l[N2 * N3];
__device__ ush g_w4_h[N3 * N4],  g_w4_l[N3 * N4];

__device__ __forceinline__ void split_bf(float v, ush& h, ush& l)
{
    __nv_bfloat16 hb = __float2bfloat16(v);           // rn
    h = __bfloat16_as_ushort(hb);
    float r = v - __bfloat162float(hb);
    l = __bfloat16_as_ushort(__float2bfloat16(r));
}

// ---------------- fused kernel 1: argmax+gather blocks, plus wsplit blocks ----
// blockIdx.x <  NROWS             : per-(b,j) argmax over heatmap + gathers
// blockIdx.x >= NROWS             : one 32x32 weight tile transpose+split
__device__ __forceinline__ void bilinear_feat(const float* __restrict__ f,
                                              int b, int bj, int C, int S,
                                              int coff, float gx, float gy)
{
    float xf = ((gx + 1.0f) * 0.5f) * (float)(S - 1);
    float yf = ((gy + 1.0f) * 0.5f) * (float)(S - 1);
    float x0f = floorf(xf), y0f = floorf(yf);
    float wx = xf - x0f,    wy = yf - y0f;
    int x0 = min(max((int)x0f, 0), S - 1);
    int x1 = min(max((int)x0f + 1, 0), S - 1);
    int y0 = min(max((int)y0f, 0), S - 1);
    int y1 = min(max((int)y0f + 1, 0), S - 1);

    float w00 = (1.0f - wx) * (1.0f - wy);
    float w01 = wx * (1.0f - wy);
    float w10 = (1.0f - wx) * wy;
    float w11 = wx * wy;

    for (int c = threadIdx.x; c < C; c += blockDim.x) {
        const float* chan = f + ((size_t)(b * C + c)) * S * S;
        float v = chan[y0 * S + x0] * w00 + chan[y0 * S + x1] * w01
                + chan[y1 * S + x0] * w10 + chan[y1 * S + x1] * w11;
        ush h, l; split_bf(v, h, l);
        g_ms_h[(size_t)bj * KIN + coff + c] = h;
        g_ms_l[(size_t)bj * KIN + coff + c] = l;
    }
}

__device__ __forceinline__ void wsplit_tile(const float* __restrict__ W,
                                            ush* __restrict__ wh, ush* __restrict__ wl,
                                            int K, int N, int kt, int nt,
                                            float (*tile)[33])
{
    const int tx = threadIdx.x & 31, ty = threadIdx.x >> 5;   // 32 x 8
    #pragma unroll
    for (int i = 0; i < 4; i++)
        tile[ty + i * 8][tx] = W[(size_t)(kt + ty + i * 8) * N + nt + tx];
    __syncthreads();
    #pragma unroll
    for (int i = 0; i < 4; i++) {
        int n = nt + ty + i * 8, k = kt + tx;
        ush h, l; split_bf(tile[tx][ty + i * 8], h, l);
        wh[(size_t)n * K + k] = h;
        wl[(size_t)n * K + k] = l;
    }
}

__global__ void fused_front_kernel(const float* __restrict__ hm,
                                   const float* __restrict__ pos_embed,
                                   const float* __restrict__ f1,
                                   const float* __restrict__ f2,
                                   const float* __restrict__ f3,
                                   const float* __restrict__ W1,
                                   const float* __restrict__ W2,
                                   const float* __restrict__ W3,
                                   const float* __restrict__ W4,
                                   ush* __restrict__ w1h, ush* __restrict__ w1l,
                                   ush* __restrict__ w2h, ush* __restrict__ w2l,
                                   ush* __restrict__ w3h, ush* __restrict__ w3l,
                                   ush* __restrict__ w4h, ush* __restrict__ w4l,
                                   float* __restrict__ out)
{
    __shared__ float sv[256];
    __shared__ int   si[256];
    __shared__ float tile[32][33];

    if (blockIdx.x >= NROWS) {
        // -------- weight split role --------
        int bi = blockIdx.x - NROWS;
        if (bi < WT1) {
            wsplit_tile(W1, w1h, w1l, KIN, N1, (bi >> 5) * 32, (bi & 31) * 32, tile);
        } else if ((bi -= WT1) < WT2) {
            wsplit_tile(W2, w2h, w2l, N1, N2, (bi >> 4) * 32, (bi & 15) * 32, tile);
        } else if ((bi -= WT2) < WT3) {
            wsplit_tile(W3, w3h, w3l, N2, N3, (bi >> 3) * 32, (bi & 7) * 32, tile);
        } else {
            bi -= WT3;
            wsplit_tile(W4, w4h, w4l, N3, N4, (bi / 7) * 32, (bi % 7) * 32, tile);
        }
        return;
    }

    // -------- argmax + gather role --------
    const int bj = blockIdx.x;
    const int b  = bj >> 6;
    const int j  = bj & 63;
    const float4* p = reinterpret_cast<const float4*>(hm + (size_t)bj * (HM_ * HM_));

    float best = __int_as_float(0xff800000);
    int   bidx = 0;

    for (int i = threadIdx.x; i < (HM_ * HM_ / 4); i += 256) {
        float4 v = p[i];
        int base = i * 4;
        if (v.x > best) { best = v.x; bidx = base;     }
        if (v.y > best) { best = v.y; bidx = base + 1; }
        if (v.z > best) { best = v.z; bidx = base + 2; }
        if (v.w > best) { best = v.w; bidx = base + 3; }
    }
    sv[threadIdx.x] = best;
    si[threadIdx.x] = bidx;
    __syncthreads();

    for (int s = 128; s > 0; s >>= 1) {
        if (threadIdx.x < s) {
            float ov = sv[threadIdx.x + s];
            int   oi = si[threadIdx.x + s];
            float mv = sv[threadIdx.x];
            if (ov > mv || (ov == mv && oi < si[threadIdx.x])) {
                sv[threadIdx.x] = ov;
                si[threadIdx.x] = oi;
            }
        }
        __syncthreads();
    }

    const int idx = si[0];
    const int px = idx & (HM_ - 1);
    const int py = idx >> 8;
    const float gx = ((float)px - 127.5f) / 127.5f;
    const float gy = ((float)py - 127.5f) / 127.5f;

    {
        float xr = ((gx + 1.0f) * 0.5f) * 255.0f;
        float yr = ((gy + 1.0f) * 0.5f) * 255.0f;
        int ix = min(max((int)rintf(xr), 0), HM_ - 1);
        int iy = min(max((int)rintf(yr), 0), HM_ - 1);
        for (int c = threadIdx.x; c < CPOS; c += 256) {
            float v = pos_embed[((size_t)(b * CPOS + c)) * (HM_ * HM_) + iy * HM_ + ix];
            out[((size_t)(b * 256) + 224 + c) * J_ + j] = v;
        }
    }

    bilinear_feat(f1, b, bj,  96, 128,   0, gx, gy);
    bilinear_feat(f2, b, bj, 384,  64,  96, gx, gy);
    bilinear_feat(f3, b, bj, 512,  32, 480, gx, gy);
}

// ---------------- kernel 2: pre-split bf16x3 tensor-core GEMM ----------------
// C = relu(A @ W + b); A,W given as bf16 hi/lo planes, A[m][k], W[n][k].
// BM=BN=BK=32, 128 threads (4 warps 2x2, warp tile 16x16), 3-stage cp.async.
#define BM    32
#define BN    32
#define BK    32
#define AROW  40                 // padded elems/row: 80B stride (16B-aligned, conflict-spread)
#define PLB   (32 * AROW * 2)    // bytes per plane per stage (2560)

#define CP16(dst, src) asm volatile("cp.async.cg.shared.global [%0], [%1], 16;" :: "r"(dst), "l"(src))
#define CP_COMMIT()    asm volatile("cp.async.commit_group;")
#define CP_WAIT(n)     asm volatile("cp.async.wait_group %0;" :: "n"(n))

#define LDSM4(R, ADDR) \
    asm volatile("ldmatrix.sync.aligned.m8n8.x4.shared.b16 {%0,%1,%2,%3}, [%4];" \
                 : "=r"((R)[0]), "=r"((R)[1]), "=r"((R)[2]), "=r"((R)[3]) : "r"(ADDR))

#define MMA16816(D, A, B0, B1) \
    asm volatile("mma.sync.aligned.m16n8k16.row.col.f32.bf16.bf16.f32 " \
                 "{%0,%1,%2,%3}, {%4,%5,%6,%7}, {%8,%9}, {%0,%1,%2,%3};" \
                 : "+f"((D)[0]), "+f"((D)[1]), "+f"((D)[2]), "+f"((D)[3]) \
                 : "r"((A)[0]), "r"((A)[1]), "r"((A)[2]), "r"((A)[3]), "r"(B0), "r"(B1))

template<bool FINAL>
__global__ __launch_bounds__(128) void gemm_bf16x3(
    const ush* __restrict__ Ah, const ush* __restrict__ Al,
    const ush* __restrict__ Wh, const ush* __restrict__ Wl,
    const float* __restrict__ bias,
    ush* __restrict__ Ch, ush* __restrict__ Cl,
    float* __restrict__ Cf, int N, int K)
{
    __shared__ __align__(16) ush sA[3][2][32 * AROW];
    __shared__ __align__(16) ush sB[3][2][32 * AROW];

    const int tid  = threadIdx.x;
    const int wid  = tid >> 5;
    const int lane = tid & 31;
    const int bm   = blockIdx.y * BM;
    const int bn   = blockIdx.x * BN;
    const int M0   = (wid >> 1) * 16;
    const int N0   = (wid & 1) * 16;
    const int gid  = lane >> 2;
    const int tig  = lane & 3;

    // cp.async mapping: thread -> (row 0..31, 16B quad 0..3)
    const int row = tid >> 2, kq = tid & 3;
    const ush* aSrcH = Ah + (size_t)(bm + row) * K + kq * 8;
    const ush* aSrcL = Al + (size_t)(bm + row) * K + kq * 8;
    const ush* bSrcH = Wh + (size_t)(bn + row) * K + kq * 8;
    const ush* bSrcL = Wl + (size_t)(bn + row) * K + kq * 8;

    const unsigned aBase = (unsigned)__cvta_generic_to_shared(&sA[0][0][0]);
    const unsigned bBase = (unsigned)__cvta_generic_to_shared(&sB[0][0][0]);
    const unsigned dOff  = (unsigned)(row * AROW + kq * 8) * 2;

    // ldmatrix x4 lane offsets: tiles (r0-7,k0-7),(r8-15,k0-7),(r0-7,k8-15),(r8-15,k8-15)
    const int ltile = lane >> 3, rin = lane & 7;
    const int rsel  = (ltile & 1) ? 8 : 0;
    const int ksel  = (ltile >= 2) ? 8 : 0;
    const unsigned aoff = (unsigned)(((M0 + rsel + rin) * AROW + ksel) * 2);
    const unsigned boff = (unsigned)(((N0 + rsel + rin) * AROW + ksel) * 2);

    float acc[2][4] = {};

    const int nch = K / BK;
    auto issue = [&](int c) {
        const int st = c % 3;
        const int k0 = c * BK;
        CP16(aBase + (st * 2 + 0) * PLB + dOff, aSrcH + k0);
        CP16(aBase + (st * 2 + 1) * PLB + dOff, aSrcL + k0);
        CP16(bBase + (st * 2 + 0) * PLB + dOff, bSrcH + k0);
        CP16(bBase + (st * 2 + 1) * PLB + dOff, bSrcL + k0);
        CP_COMMIT();
    };

    issue(0);
    issue(1);

    for (int c = 0; c < nch; c++) {
        if (c < nch - 1) { CP_WAIT(1); } else { CP_WAIT(0); }
        __syncthreads();

        const int st = c % 3;
        const unsigned aH = aBase + (st * 2 + 0) * PLB;
        const unsigned aL = aH + PLB;
        const unsigned bH = bBase + (st * 2 + 0) * PLB;
        const unsigned bL = bH + PLB;

        #pragma unroll
        for (int kk = 0; kk < BK; kk += 16) {
            unsigned a_hi[4], a_lo[4], b_hi[4], b_lo[4];
            LDSM4(a_hi, aH + aoff + kk * 2);
            LDSM4(a_lo, aL + aoff + kk * 2);
            LDSM4(b_hi, bH + boff + kk * 2);
            LDSM4(b_lo, bL + boff + kk * 2);
            #pragma unroll
            for (int ni = 0; ni < 2; ni++) {
                MMA16816(acc[ni], a_hi, b_hi[ni], b_hi[ni + 2]);
                MMA16816(acc[ni], a_hi, b_lo[ni], b_lo[ni + 2]);
                MMA16816(acc[ni], a_lo, b_hi[ni], b_hi[ni + 2]);
            }
        }

        if (c + 2 < nch) issue(c + 2);
    }

    // ---- epilogue ----
    const int r0 = bm + M0 + gid;
    const int r1 = r0 + 8;
    #pragma unroll
    for (int ni = 0; ni < 2; ni++) {
        const int n = bn + N0 + ni * 8 + tig * 2;
        const float bv0 = bias[n], bv1 = bias[n + 1];
        float v00 = fmaxf(acc[ni][0] + bv0, 0.0f);
        float v01 = fmaxf(acc[ni][1] + bv1, 0.0f);
        float v10 = fmaxf(acc[ni][2] + bv0, 0.0f);
        float v11 = fmaxf(acc[ni][3] + bv1, 0.0f);
        if (FINAL) {
            const int b0 = r0 >> 6, j0 = r0 & 63;
            const int b1 = r1 >> 6, j1 = r1 & 63;
            Cf[((size_t)(b0 * 256) + n    ) * J_ + j0] = v00;
            Cf[((size_t)(b0 * 256) + n + 1) * J_ + j0] = v01;
            Cf[((size_t)(b1 * 256) + n    ) * J_ + j1] = v10;
            Cf[((size_t)(b1 * 256) + n + 1) * J_ + j1] = v11;
        } else {
            ush h0, l0, h1, l1;
            split_bf(v00, h0, l0); split_bf(v01, h1, l1);
            *reinterpret_cast<unsigned*>(&Ch[(size_t)r0 * N + n]) = (unsigned)h0 | ((unsigned)h1 << 16);
            *reinterpret_cast<unsigned*>(&Cl[(size_t)r0 * N + n]) = (unsigned)l0 | ((unsigned)l1 << 16);
            split_bf(v10, h0, l0); split_bf(v11, h1, l1);
            *reinterpret_cast<unsigned*>(&Ch[(size_t)r1 * N + n]) = (unsigned)h0 | ((unsigned)h1 << 16);
            *reinterpret_cast<unsigned*>(&Cl[(size_t)r1 * N + n]) = (unsigned)l0 | ((unsigned)l1 << 16);
        }
    }
}

// ---------------- launch ----------------
extern "C" void kernel_launch(void* const* d_in, const int* in_sizes, int n_in,
                              void* d_out, int out_size)
{
    const float* heatmap   = (const float*)d_in[0];
    const float* pos_embed = (const float*)d_in[1];
    const float* f1        = (const float*)d_in[2];
    const float* f2        = (const float*)d_in[3];
    const float* f3        = (const float*)d_in[4];
    const float* W1        = (const float*)d_in[5];
    const float* b1        = (const float*)d_in[6];
    const float* W2        = (const float*)d_in[7];
    const float* b2        = (const float*)d_in[8];
    const float* W3        = (const float*)d_in[9];
    const float* b3        = (const float*)d_in[10];
    const float* W4        = (const float*)d_in[11];
    const float* b4        = (const float*)d_in[12];
    float* out = (float*)d_out;

    ush *msh, *msl, *h1h, *h1l, *h2h, *h2l, *h3h, *h3l;
    ush *w1h, *w1l, *w2h, *w2l, *w3h, *w3l, *w4h, *w4l;
    cudaGetSymbolAddress((void**)&msh, g_ms_h); cudaGetSymbolAddress((void**)&msl, g_ms_l);
    cudaGetSymbolAddress((void**)&h1h, g_h1_h); cudaGetSymbolAddress((void**)&h1l, g_h1_l);
    cudaGetSymbolAddress((void**)&h2h, g_h2_h); cudaGetSymbolAddress((void**)&h2l, g_h2_l);
    cudaGetSymbolAddress((void**)&h3h, g_h3_h); cudaGetSymbolAddress((void**)&h3l, g_h3_l);
    cudaGetSymbolAddress((void**)&w1h, g_w1_h); cudaGetSymbolAddress((void**)&w1l, g_w1_l);
    cudaGetSymbolAddress((void**)&w2h, g_w2_h); cudaGetSymbolAddress((void**)&w2l, g_w2_l);
    cudaGetSymbolAddress((void**)&w3h, g_w3_h); cudaGetSymbolAddress((void**)&w3l, g_w3_l);
    cudaGetSymbolAddress((void**)&w4h, g_w4_h); cudaGetSymbolAddress((void**)&w4l, g_w4_l);

    fused_front_kernel<<<NROWS + WT_ALL, 256>>>(
        heatmap, pos_embed, f1, f2, f3,
        W1, W2, W3, W4,
        w1h, w1l, w2h, w2l, w3h, w3l, w4h, w4l, out);

    gemm_bf16x3<false><<<dim3(N1 / BN, NROWS / BM), 128>>>(msh, msl, w1h, w1l, b1, h1h, h1l, nullptr, N1, KIN);
    gemm_bf16x3<false><<<dim3(N2 / BN, NROWS / BM), 128>>>(h1h, h1l, w2h, w2l, b2, h2h, h2l, nullptr, N2, N1);
    gemm_bf16x3<false><<<dim3(N3 / BN, NROWS / BM), 128>>>(h2h, h2l, w3h, w3l, b3, h3h, h3l, nullptr, N3, N2);
    gemm_bf16x3<true ><<<dim3(N4 / BN, NROWS / BM), 128>>>(h3h, h3l, w4h, w4l, b4, nullptr, nullptr, out, N4, N3);
}